// round 3
// baseline (speedup 1.0000x reference)
#include <cuda_runtime.h>
#include <math_constants.h>

#define D       256
#define NT      65536
#define NE      4096
#define BM      128
#define BN      128
#define BK      16
#define BMP     132   // pad 128->132: keeps 16B alignment per k-row, 2-way store conflicts only

typedef unsigned long long u64;

__device__ float g_eNormHalf[NE];
__device__ int   g_idx[NT];

__device__ __forceinline__ u64 pack_dup(float x) {
    u64 r;
    asm("mov.b64 %0, {%1, %1};" : "=l"(r) : "f"(x));
    return r;
}
__device__ __forceinline__ void ffma2(u64& acc, u64 a, u64 b) {
    asm("fma.rn.f32x2 %0, %1, %2, %0;" : "+l"(acc) : "l"(a), "l"(b));
}
__device__ __forceinline__ void unpack2(u64 v, float& lo, float& hi) {
    asm("mov.b64 {%0, %1}, %2;" : "=f"(lo), "=f"(hi) : "l"(v));
}

// ---------------------------------------------------------------------------
// Kernel 1: 0.5 * ||e||^2 per codebook row. One warp per row.
// ---------------------------------------------------------------------------
__global__ void enorm_kernel(const float* __restrict__ e) {
    int row  = blockIdx.x * (blockDim.x >> 5) + (threadIdx.x >> 5);
    int lane = threadIdx.x & 31;
    if (row >= NE) return;
    const float4* p = (const float4*)(e + row * D);
    float s = 0.f;
    #pragma unroll
    for (int i = lane; i < D / 4; i += 32) {
        float4 v = p[i];
        s += v.x * v.x + v.y * v.y + v.z * v.z + v.w * v.w;
    }
    #pragma unroll
    for (int o = 16; o; o >>= 1) s += __shfl_xor_sync(0xFFFFFFFFu, s, o);
    if (lane == 0) g_eNormHalf[row] = 0.5f * s;
}

// ---------------------------------------------------------------------------
// Kernel 2: fused GEMM + argmin using packed fp32x2 FMAs (FFMA2).
// 256 threads as 16x16; thread (tx,ty) owns rows ty*8..+7, cols tx*8..+7.
// Accumulators are 8x4 packed f32x2 (8 rows x 4 column-pairs).
// score = ||e||^2/2 - z.e   (||z||^2 is a per-token constant).
// ---------------------------------------------------------------------------
__global__ __launch_bounds__(256, 2)
void argmin_kernel(const float* __restrict__ z, const float* __restrict__ e) {
    __shared__ float As[BK][BMP];
    __shared__ float Bs[BK][BMP];
    __shared__ float redS[BM][17];
    __shared__ int   redI[BM][17];

    const int tid = threadIdx.x;
    const int tx  = tid & 15;
    const int ty  = tid >> 4;
    const int m0  = blockIdx.x * BM;

    float bestS[8];
    int   bestI[8];
    #pragma unroll
    for (int i = 0; i < 8; i++) { bestS[i] = CUDART_INF_F; bestI[i] = 0; }

    for (int n0 = 0; n0 < NE; n0 += BN) {
        u64 acc2[8][4];
        #pragma unroll
        for (int i = 0; i < 8; i++)
            #pragma unroll
            for (int j = 0; j < 4; j++) acc2[i][j] = 0ull;  // {0.f, 0.f}

        for (int k0 = 0; k0 < D; k0 += BK) {
            // cooperative transpose-load: 2048 elems each of A,B; 8 per thread
            #pragma unroll
            for (int r = 0; r < 8; r++) {
                int eidx = tid + r * 256;
                int m    = eidx >> 4;
                int k    = eidx & 15;
                As[k][m] = z[(m0 + m) * D + k0 + k];
                Bs[k][m] = e[(n0 + m) * D + k0 + k];
            }
            __syncthreads();

            #pragma unroll
            for (int k = 0; k < BK; k++) {
                const float4* arow = (const float4*)&As[k][ty * 8];
                float4 al = arow[0];
                float4 ah = arow[1];
                u64 a2[8];
                a2[0] = pack_dup(al.x); a2[1] = pack_dup(al.y);
                a2[2] = pack_dup(al.z); a2[3] = pack_dup(al.w);
                a2[4] = pack_dup(ah.x); a2[5] = pack_dup(ah.y);
                a2[6] = pack_dup(ah.z); a2[7] = pack_dup(ah.w);

                const u64* brow = (const u64*)&Bs[k][tx * 8];
                u64 b2[4];
                b2[0] = brow[0]; b2[1] = brow[1];
                b2[2] = brow[2]; b2[3] = brow[3];

                #pragma unroll
                for (int i = 0; i < 8; i++)
                    #pragma unroll
                    for (int j = 0; j < 4; j++)
                        ffma2(acc2[i][j], a2[i], b2[j]);
            }
            __syncthreads();
        }

        // fold this code-tile into the running argmin
        const float4* en4 = (const float4*)&g_eNormHalf[n0 + tx * 8];
        float4 e_lo = en4[0];
        float4 e_hi = en4[1];
        float en[8] = {e_lo.x, e_lo.y, e_lo.z, e_lo.w,
                       e_hi.x, e_hi.y, e_hi.z, e_hi.w};
        int nbase = n0 + tx * 8;
        #pragma unroll
        for (int i = 0; i < 8; i++) {
            #pragma unroll
            for (int j = 0; j < 4; j++) {
                float d0, d1;
                unpack2(acc2[i][j], d0, d1);
                float s0 = en[2 * j]     - d0;
                float s1 = en[2 * j + 1] - d1;
                if (s0 < bestS[i]) { bestS[i] = s0; bestI[i] = nbase + 2 * j; }
                if (s1 < bestS[i]) { bestS[i] = s1; bestI[i] = nbase + 2 * j + 1; }
            }
        }
    }

    // reduce across the 16 tx-threads sharing each token row
    #pragma unroll
    for (int i = 0; i < 8; i++) {
        redS[ty * 8 + i][tx] = bestS[i];
        redI[ty * 8 + i][tx] = bestI[i];
    }
    __syncthreads();
    if (tid < BM) {
        float bs = redS[tid][0];
        int   bi = redI[tid][0];
        #pragma unroll
        for (int t = 1; t < 16; t++) {
            float s = redS[tid][t];
            int   n = redI[tid][t];
            if (s < bs || (s == bs && n < bi)) { bs = s; bi = n; }
        }
        g_idx[m0 + tid] = bi;
    }
}

// ---------------------------------------------------------------------------
// Kernel 3: gather z_quantized = embedding[idx], float4 at a time.
// ---------------------------------------------------------------------------
__global__ void gather_kernel(const float* __restrict__ e,
                              float* __restrict__ out,
                              int write_idx_tail) {
    int t   = blockIdx.x * blockDim.x + threadIdx.x;   // over NT * (D/4)
    int row = t >> 6;       // D/4 = 64 float4 per row
    int c   = t & 63;
    int idx = g_idx[row];
    ((float4*)out)[t] = ((const float4*)(e + idx * D))[c];
    if (write_idx_tail && c == 0) {
        out[NT * D + row] = (float)idx;
    }
}

extern "C" void kernel_launch(void* const* d_in, const int* in_sizes, int n_in,
                              void* d_out, int out_size) {
    const float* z = (const float*)d_in[0];
    const float* e = (const float*)d_in[1];
    float* out = (float*)d_out;

    int write_idx_tail = (out_size >= NT * D + NT) ? 1 : 0;

    enorm_kernel<<<NE / 8, 256>>>(e);
    argmin_kernel<<<NT / BM, 256>>>(z, e);
    gather_kernel<<<(NT * (D / 4)) / 256, 256>>>(e, out, write_idx_tail);
}

// round 5
// speedup vs baseline: 3.0579x; 3.0579x over previous
#include <cuda_runtime.h>
#include <cuda_bf16.h>
#include <cstdint>
#include <math_constants.h>

#define D       256
#define NT      65536
#define NE      4096
#define WINDOW  0.01f

// ---- smem layout (bytes) ----
#define APITCH  528                       // 264 bf16 per A row (256 data + 8 pad)
#define AH_OFF  0
#define AL_OFF  (128 * APITCH)            // 67584
#define BB_OFF  (2 * 128 * APITCH)        // 135168
#define BPITCH  80                        // 40 bf16 per B row (32 data + 8 pad)
#define BLO     (128 * BPITCH)            // 10240 (lo image within a stage)
#define BSTAGE  (2 * 128 * BPITCH)        // 20480 (hi+lo)
#define RED_OFF BB_OFF                    // reduction arrays alias B buffers
#define SMEM_TOTAL (BB_OFF + 2 * BSTAGE)  // 176128

__device__ float g_eNormHalf[NE];
__device__ int   g_idx[NT];
__device__ int   g_ambCount;
__device__ int   g_ambList[NT];
__device__ __nv_bfloat16 g_eH[NE * D];
__device__ __nv_bfloat16 g_eL[NE * D];

// ---------------- helpers ----------------
__device__ __forceinline__ uint32_t smem_u32(const void* p) {
    uint32_t a;
    asm("{ .reg .u64 t; cvta.to.shared.u64 t, %1; cvt.u32.u64 %0, t; }" : "=r"(a) : "l"(p));
    return a;
}
__device__ __forceinline__ void ldsm4(uint32_t (&r)[4], uint32_t a) {
    asm volatile("ldmatrix.sync.aligned.m8n8.x4.shared.b16 {%0,%1,%2,%3}, [%4];"
                 : "=r"(r[0]), "=r"(r[1]), "=r"(r[2]), "=r"(r[3]) : "r"(a));
}
__device__ __forceinline__ void mma16816(float (&c)[4], const uint32_t (&a)[4],
                                         uint32_t b0, uint32_t b1) {
    asm volatile("mma.sync.aligned.m16n8k16.row.col.f32.bf16.bf16.f32 "
                 "{%0,%1,%2,%3}, {%4,%5,%6,%7}, {%8,%9}, {%0,%1,%2,%3};"
                 : "+f"(c[0]), "+f"(c[1]), "+f"(c[2]), "+f"(c[3])
                 : "r"(a[0]), "r"(a[1]), "r"(a[2]), "r"(a[3]), "r"(b0), "r"(b1));
}

// ---------------------------------------------------------------------------
// enorm: 0.5*||e||^2 (fp32 exact, shared by approx + exact paths)
// ---------------------------------------------------------------------------
__global__ void enorm_kernel(const float* __restrict__ e) {
    int row  = blockIdx.x * (blockDim.x >> 5) + (threadIdx.x >> 5);
    int lane = threadIdx.x & 31;
    const float4* p = (const float4*)(e + row * D);
    float s = 0.f;
    #pragma unroll
    for (int i = lane; i < D / 4; i += 32) {
        float4 v = p[i];
        s += v.x * v.x + v.y * v.y + v.z * v.z + v.w * v.w;
    }
    #pragma unroll
    for (int o = 16; o; o >>= 1) s += __shfl_xor_sync(0xFFFFFFFFu, s, o);
    if (lane == 0) g_eNormHalf[row] = 0.5f * s;
}

// ---------------------------------------------------------------------------
// e split to bf16 hi/lo images (row-major), also zeroes the ambiguity counter
// ---------------------------------------------------------------------------
__global__ void esplit_kernel(const float* __restrict__ e) {
    int idx = blockIdx.x * 256 + threadIdx.x;
    if (idx == 0) g_ambCount = 0;
    float v = e[idx];
    __nv_bfloat16 h = __float2bfloat16(v);
    g_eH[idx] = h;
    g_eL[idx] = __float2bfloat16(v - __bfloat162float(h));
}

// ---------------------------------------------------------------------------
// double-buffered cp.async fill of one e k-chunk (128 codes x 32 dims, hi+lo)
// ---------------------------------------------------------------------------
__device__ __forceinline__ void issue_chunk(uint32_t sbase, int c, int tid) {
    const int n0 = (c >> 3) * 128;
    const int k0 = (c & 7) * 32;
    const uint32_t sb = sbase + BB_OFF + (uint32_t)(c & 1) * BSTAGE;
    #pragma unroll
    for (int j = 0; j < 4; j++) {
        int lin  = tid + j * 256;           // 0..1023
        int hilo = lin >> 9;
        int rem  = lin & 511;
        int row  = rem >> 2;
        int off  = (rem & 3) * 16;
        const char* g = (const char*)(hilo ? g_eL : g_eH)
                        + (size_t)(n0 + row) * (D * 2) + k0 * 2 + off;
        uint32_t s = sb + (uint32_t)hilo * BLO + (uint32_t)(row * BPITCH) + off;
        asm volatile("cp.async.cg.shared.global [%0], [%1], 16;" :: "r"(s), "l"(g));
    }
}

// ---------------------------------------------------------------------------
// fused HMMA GEMM + best-2 argmin. 256 threads, warps 4(m) x 2(n) over 128x128.
// ---------------------------------------------------------------------------
__global__ __launch_bounds__(256, 1)
void argmin_mma(const float* __restrict__ z) {
    extern __shared__ unsigned char sm[];
    const uint32_t sbase = smem_u32(sm);

    const int tid  = threadIdx.x;
    const int lane = tid & 31, wid = tid >> 5;
    const int warp_m = wid & 3, warp_n = wid >> 2;
    const int gid = lane >> 2, tig = lane & 3;
    const int sub = lane >> 3, r7 = lane & 7;
    const int m0 = blockIdx.x * 128;

    // ---- load z tile, split to bf16 hi/lo in smem (row-major, padded) ----
    for (int i = tid; i < 128 * 64; i += 256) {
        int m = i >> 6, k4 = i & 63;
        float4 v = ((const float4*)(z + (size_t)(m0 + m) * D))[k4];
        unsigned short hx = __bfloat16_as_ushort(__float2bfloat16(v.x));
        unsigned short hy = __bfloat16_as_ushort(__float2bfloat16(v.y));
        unsigned short hz = __bfloat16_as_ushort(__float2bfloat16(v.z));
        unsigned short hw = __bfloat16_as_ushort(__float2bfloat16(v.w));
        float lx = v.x - __bfloat162float(__ushort_as_bfloat16(hx));
        float ly = v.y - __bfloat162float(__ushort_as_bfloat16(hy));
        float lz = v.z - __bfloat162float(__ushort_as_bfloat16(hz));
        float lw = v.w - __bfloat162float(__ushort_as_bfloat16(hw));
        uint2 hv, lv;
        hv.x = (uint32_t)hx | ((uint32_t)hy << 16);
        hv.y = (uint32_t)hz | ((uint32_t)hw << 16);
        lv.x = (uint32_t)__bfloat16_as_ushort(__float2bfloat16(lx)) |
               ((uint32_t)__bfloat16_as_ushort(__float2bfloat16(ly)) << 16);
        lv.y = (uint32_t)__bfloat16_as_ushort(__float2bfloat16(lz)) |
               ((uint32_t)__bfloat16_as_ushort(__float2bfloat16(lw)) << 16);
        *(uint2*)(sm + AH_OFF + m * APITCH + k4 * 8) = hv;
        *(uint2*)(sm + AL_OFF + m * APITCH + k4 * 8) = lv;
    }

    // ldmatrix per-thread base addresses
    const uint32_t aBase = sbase + AH_OFF +
        (uint32_t)((warp_m * 32 + (sub & 1) * 8 + r7) * APITCH) + (uint32_t)((sub >> 1) * 16);
    const uint32_t bRow =
        (uint32_t)((warp_n * 64 + (sub >> 1) * 8 + r7) * BPITCH) + (uint32_t)((sub & 1) * 16);

    float acc[2][8][4];
    #pragma unroll
    for (int mt = 0; mt < 2; mt++)
        #pragma unroll
        for (int nt = 0; nt < 8; nt++)
            #pragma unroll
            for (int q = 0; q < 4; q++) acc[mt][nt][q] = 0.f;

    float bS1[4], bS2[4];
    int   bI1[4];
    #pragma unroll
    for (int i = 0; i < 4; i++) { bS1[i] = CUDART_INF_F; bS2[i] = CUDART_INF_F; bI1[i] = 0; }

    issue_chunk(sbase, 0, tid);
    asm volatile("cp.async.commit_group;" ::: "memory");
    __syncthreads();   // z smem visible to all; chunk0 in flight

    for (int c = 0; c < 256; c++) {
        if (c + 1 < 256) issue_chunk(sbase, c + 1, tid);
        asm volatile("cp.async.commit_group;" ::: "memory");
        asm volatile("cp.async.wait_group 1;" ::: "memory");
        __syncthreads();

        const uint32_t kA = (uint32_t)((c & 7) * 64);
        const uint32_t bStage = sbase + BB_OFF + (uint32_t)(c & 1) * BSTAGE;

        #pragma unroll
        for (int ks = 0; ks < 2; ks++) {
            uint32_t ah[2][4], al[2][4];
            #pragma unroll
            for (int mt = 0; mt < 2; mt++) {
                uint32_t a = aBase + (uint32_t)(mt * 16 * APITCH) + kA + ks * 32;
                ldsm4(ah[mt], a);
                ldsm4(al[mt], a + AL_OFF);
            }
            uint32_t bh[8][2], bl[8][2];
            #pragma unroll
            for (int p = 0; p < 4; p++) {
                uint32_t b = bStage + bRow + (uint32_t)(p * 16 * BPITCH) + ks * 32;
                uint32_t t[4];
                ldsm4(t, b);
                bh[2*p][0] = t[0]; bh[2*p][1] = t[1];
                bh[2*p+1][0] = t[2]; bh[2*p+1][1] = t[3];
                ldsm4(t, b + BLO);
                bl[2*p][0] = t[0]; bl[2*p][1] = t[1];
                bl[2*p+1][0] = t[2]; bl[2*p+1][1] = t[3];
            }
            #pragma unroll
            for (int mt = 0; mt < 2; mt++)
                #pragma unroll
                for (int nt = 0; nt < 8; nt++) {
                    mma16816(acc[mt][nt], ah[mt], bh[nt][0], bh[nt][1]);
                    mma16816(acc[mt][nt], ah[mt], bl[nt][0], bl[nt][1]);
                    mma16816(acc[mt][nt], al[mt], bh[nt][0], bh[nt][1]);
                }
        }

        if ((c & 7) == 7) {   // code tile complete: fold into best-2, reset acc
            const int n0 = (c >> 3) * 128;
            #pragma unroll
            for (int nt = 0; nt < 8; nt++) {
                int nb = n0 + warp_n * 64 + nt * 8 + tig * 2;
                float2 en = *(const float2*)&g_eNormHalf[nb];
                #pragma unroll
                for (int mt = 0; mt < 2; mt++) {
                    float s0 = en.x - acc[mt][nt][0];
                    float s1 = en.y - acc[mt][nt][1];
                    float s2 = en.x - acc[mt][nt][2];
                    float s3 = en.y - acc[mt][nt][3];
                    int lr0 = mt * 2, lr1 = mt * 2 + 1;
                    if (s0 < bS1[lr0]) { bS2[lr0] = bS1[lr0]; bS1[lr0] = s0; bI1[lr0] = nb; }
                    else if (s0 < bS2[lr0]) bS2[lr0] = s0;
                    if (s1 < bS1[lr0]) { bS2[lr0] = bS1[lr0]; bS1[lr0] = s1; bI1[lr0] = nb + 1; }
                    else if (s1 < bS2[lr0]) bS2[lr0] = s1;
                    if (s2 < bS1[lr1]) { bS2[lr1] = bS1[lr1]; bS1[lr1] = s2; bI1[lr1] = nb; }
                    else if (s2 < bS2[lr1]) bS2[lr1] = s2;
                    if (s3 < bS1[lr1]) { bS2[lr1] = bS1[lr1]; bS1[lr1] = s3; bI1[lr1] = nb + 1; }
                    else if (s3 < bS2[lr1]) bS2[lr1] = s3;
                    acc[mt][nt][0] = 0.f; acc[mt][nt][1] = 0.f;
                    acc[mt][nt][2] = 0.f; acc[mt][nt][3] = 0.f;
                }
            }
        }
        __syncthreads();
    }

    // ---- cross-thread best-2 merge (8 slots per token row) ----
    float* rS1 = (float*)(sm + RED_OFF);
    float* rS2 = (float*)(sm + RED_OFF + 4096);
    int*   rI  = (int*)  (sm + RED_OFF + 8192);
    const int slot = warp_n * 4 + tig;
    #pragma unroll
    for (int lr = 0; lr < 4; lr++) {
        int r = warp_m * 32 + (lr >> 1) * 16 + (lr & 1) * 8 + gid;
        rS1[r * 8 + slot] = bS1[lr];
        rS2[r * 8 + slot] = bS2[lr];
        rI [r * 8 + slot] = bI1[lr];
    }
    __syncthreads();
    if (tid < 128) {
        float b1 = CUDART_INF_F, b2 = CUDART_INF_F;
        int bi = 0x7FFFFFFF;
        #pragma unroll
        for (int s = 0; s < 8; s++) {
            float s1 = rS1[tid * 8 + s];
            float s2 = rS2[tid * 8 + s];
            int   i1 = rI [tid * 8 + s];
            if (s1 < b1 || (s1 == b1 && i1 < bi)) {
                b2 = fminf(b2, fminf(b1, s2));
                b1 = s1; bi = i1;
            } else {
                b2 = fminf(b2, s1);
            }
        }
        g_idx[m0 + tid] = bi;
        if (b2 - b1 <= WINDOW) {
            int p = atomicAdd(&g_ambCount, 1);
            g_ambList[p] = m0 + tid;
        }
    }
}

// ---------------------------------------------------------------------------
// fixup: exact fp32 argmin for ambiguous tokens (lowest-index tie-break)
// ---------------------------------------------------------------------------
__global__ void fixup_kernel(const float* __restrict__ z, const float* __restrict__ e) {
    __shared__ __align__(16) float sz[D];
    __shared__ float rs[256];
    __shared__ int   ri[256];
    const int tid = threadIdx.x;
    const int cnt = g_ambCount;
    for (int li = blockIdx.x; li < cnt; li += gridDim.x) {
        int m = g_ambList[li];
        sz[tid] = z[(size_t)m * D + tid];
        __syncthreads();
        float bs = CUDART_INF_F;
        int   bi = 0x7FFFFFFF;
        for (int rep = 0; rep < NE / 256; rep++) {
            int n = rep * 256 + tid;
            float acc = 0.f;
            const float4* er = (const float4*)(e + (size_t)n * D);
            const float4* zr = (const float4*)sz;
            #pragma unroll 8
            for (int k4 = 0; k4 < D / 4; k4++) {
                float4 ee = er[k4], zz = zr[k4];
                acc = __fmaf_rn(zz.x, ee.x, acc);
                acc = __fmaf_rn(zz.y, ee.y, acc);
                acc = __fmaf_rn(zz.z, ee.z, acc);
                acc = __fmaf_rn(zz.w, ee.w, acc);
            }
            float s = g_eNormHalf[n] - acc;
            if (s < bs || (s == bs && n < bi)) { bs = s; bi = n; }
        }
        rs[tid] = bs; ri[tid] = bi;
        __syncthreads();
        if (tid == 0) {
            float b = rs[0]; int i = ri[0];
            for (int t = 1; t < 256; t++)
                if (rs[t] < b || (rs[t] == b && ri[t] < i)) { b = rs[t]; i = ri[t]; }
            g_idx[m] = i;
        }
        __syncthreads();
    }
}

// ---------------------------------------------------------------------------
// gather
// ---------------------------------------------------------------------------
__global__ void gather_kernel(const float* __restrict__ e,
                              float* __restrict__ out, int write_idx_tail) {
    int t   = blockIdx.x * blockDim.x + threadIdx.x;
    int row = t >> 6;
    int c   = t & 63;
    int idx = g_idx[row];
    ((float4*)out)[t] = ((const float4*)(e + (size_t)idx * D))[c];
    if (write_idx_tail && c == 0) out[NT * D + row] = (float)idx;
}

extern "C" void kernel_launch(void* const* d_in, const int* in_sizes, int n_in,
                              void* d_out, int out_size) {
    const float* z = (const float*)d_in[0];
    const float* e = (const float*)d_in[1];
    float* out = (float*)d_out;
    int write_idx_tail = (out_size >= NT * D + NT) ? 1 : 0;

    cudaFuncSetAttribute(argmin_mma, cudaFuncAttributeMaxDynamicSharedMemorySize, SMEM_TOTAL);

    enorm_kernel<<<NE / 8, 256>>>(e);
    esplit_kernel<<<(NE * D) / 256, 256>>>(e);
    argmin_mma<<<NT / 128, 256, SMEM_TOTAL>>>(z);
    fixup_kernel<<<128, 256>>>(z, e);
    gather_kernel<<<(NT * (D / 4)) / 256, 256>>>(e, out, write_idx_tail);
}

// round 6
// speedup vs baseline: 3.2873x; 1.0750x over previous
#include <cuda_runtime.h>
#include <cuda_bf16.h>
#include <cstdint>
#include <math_constants.h>

#define D       256
#define NT      65536
#define NE      4096
#define WINDOW  0.003f

// ---- smem layout (bytes) ----
#define APITCH  528                       // 264 bf16 per A row (256 data + 8 pad)
#define AH_OFF  0
#define AL_OFF  (128 * APITCH)            // 67584
#define BB_OFF  (2 * 128 * APITCH)        // 135168
#define BPITCH  80                        // 40 bf16 per B row (32 data + 8 pad)
#define BLO     (128 * BPITCH)            // 10240 (lo image within a stage)
#define BSTAGE  (2 * 128 * BPITCH)        // 20480 (hi+lo)
#define NSTAGE  3
#define RED_OFF BB_OFF                    // reduction arrays alias B buffers
#define SMEM_TOTAL (BB_OFF + NSTAGE * BSTAGE)  // 196608 (192KB)

__device__ float g_eNormHalf[NE];
__device__ int   g_idx[NT];
__device__ int   g_ambCount;
__device__ int   g_ambList[NT];
__device__ __nv_bfloat16 g_eH[NE * D];
__device__ __nv_bfloat16 g_eL[NE * D];

// ---------------- helpers ----------------
__device__ __forceinline__ uint32_t smem_u32(const void* p) {
    uint32_t a;
    asm("{ .reg .u64 t; cvta.to.shared.u64 t, %1; cvt.u32.u64 %0, t; }" : "=r"(a) : "l"(p));
    return a;
}
__device__ __forceinline__ void ldsm4(uint32_t (&r)[4], uint32_t a) {
    asm volatile("ldmatrix.sync.aligned.m8n8.x4.shared.b16 {%0,%1,%2,%3}, [%4];"
                 : "=r"(r[0]), "=r"(r[1]), "=r"(r[2]), "=r"(r[3]) : "r"(a));
}
__device__ __forceinline__ void mma16816(float (&c)[4], const uint32_t (&a)[4],
                                         uint32_t b0, uint32_t b1) {
    asm volatile("mma.sync.aligned.m16n8k16.row.col.f32.bf16.bf16.f32 "
                 "{%0,%1,%2,%3}, {%4,%5,%6,%7}, {%8,%9}, {%0,%1,%2,%3};"
                 : "+f"(c[0]), "+f"(c[1]), "+f"(c[2]), "+f"(c[3])
                 : "r"(a[0]), "r"(a[1]), "r"(a[2]), "r"(a[3]), "r"(b0), "r"(b1));
}

// ---------------------------------------------------------------------------
// enorm: 0.5*||e||^2 (fp32 exact, shared by approx + exact paths)
// ---------------------------------------------------------------------------
__global__ void enorm_kernel(const float* __restrict__ e) {
    int row  = blockIdx.x * (blockDim.x >> 5) + (threadIdx.x >> 5);
    int lane = threadIdx.x & 31;
    const float4* p = (const float4*)(e + row * D);
    float s = 0.f;
    #pragma unroll
    for (int i = lane; i < D / 4; i += 32) {
        float4 v = p[i];
        s += v.x * v.x + v.y * v.y + v.z * v.z + v.w * v.w;
    }
    #pragma unroll
    for (int o = 16; o; o >>= 1) s += __shfl_xor_sync(0xFFFFFFFFu, s, o);
    if (lane == 0) g_eNormHalf[row] = 0.5f * s;
}

// ---------------------------------------------------------------------------
// e split to bf16 hi/lo images (row-major), also zeroes the ambiguity counter
// ---------------------------------------------------------------------------
__global__ void esplit_kernel(const float* __restrict__ e) {
    int idx = blockIdx.x * 256 + threadIdx.x;
    if (idx == 0) g_ambCount = 0;
    float v = e[idx];
    __nv_bfloat16 h = __float2bfloat16(v);
    g_eH[idx] = h;
    g_eL[idx] = __float2bfloat16(v - __bfloat162float(h));
}

// ---------------------------------------------------------------------------
// cp.async fill of one e k-chunk (128 codes x 32 dims, hi+lo) into stage c%3
// ---------------------------------------------------------------------------
__device__ __forceinline__ void issue_chunk(uint32_t sbase, int c, int tid) {
    const int n0 = (c >> 3) * 128;
    const int k0 = (c & 7) * 32;
    const uint32_t sb = sbase + BB_OFF + (uint32_t)(c % NSTAGE) * BSTAGE;
    #pragma unroll
    for (int j = 0; j < 4; j++) {
        int lin  = tid + j * 256;           // 0..1023
        int hilo = lin >> 9;
        int rem  = lin & 511;
        int row  = rem >> 2;
        int off  = (rem & 3) * 16;
        const char* g = (const char*)(hilo ? g_eL : g_eH)
                        + (size_t)(n0 + row) * (D * 2) + k0 * 2 + off;
        uint32_t s = sb + (uint32_t)hilo * BLO + (uint32_t)(row * BPITCH) + off;
        asm volatile("cp.async.cg.shared.global [%0], [%1], 16;" :: "r"(s), "l"(g));
    }
}

// ---------------------------------------------------------------------------
// fused HMMA GEMM + best-2 argmin. 256 threads, warps 4(m) x 2(n) over 128x128.
// 3-stage B pipeline, one __syncthreads per chunk.
// ---------------------------------------------------------------------------
__global__ __launch_bounds__(256, 1)
void argmin_mma(const float* __restrict__ z) {
    extern __shared__ unsigned char sm[];
    const uint32_t sbase = smem_u32(sm);

    const int tid  = threadIdx.x;
    const int lane = tid & 31, wid = tid >> 5;
    const int warp_m = wid & 3, warp_n = wid >> 2;
    const int gid = lane >> 2, tig = lane & 3;
    const int sub = lane >> 3, r7 = lane & 7;
    const int m0 = blockIdx.x * 128;

    // ---- load z tile, split to bf16 hi/lo in smem (row-major, padded) ----
    for (int i = tid; i < 128 * 64; i += 256) {
        int m = i >> 6, k4 = i & 63;
        float4 v = ((const float4*)(z + (size_t)(m0 + m) * D))[k4];
        unsigned short hx = __bfloat16_as_ushort(__float2bfloat16(v.x));
        unsigned short hy = __bfloat16_as_ushort(__float2bfloat16(v.y));
        unsigned short hz = __bfloat16_as_ushort(__float2bfloat16(v.z));
        unsigned short hw = __bfloat16_as_ushort(__float2bfloat16(v.w));
        float lx = v.x - __bfloat162float(__ushort_as_bfloat16(hx));
        float ly = v.y - __bfloat162float(__ushort_as_bfloat16(hy));
        float lz = v.z - __bfloat162float(__ushort_as_bfloat16(hz));
        float lw = v.w - __bfloat162float(__ushort_as_bfloat16(hw));
        uint2 hv, lv;
        hv.x = (uint32_t)hx | ((uint32_t)hy << 16);
        hv.y = (uint32_t)hz | ((uint32_t)hw << 16);
        lv.x = (uint32_t)__bfloat16_as_ushort(__float2bfloat16(lx)) |
               ((uint32_t)__bfloat16_as_ushort(__float2bfloat16(ly)) << 16);
        lv.y = (uint32_t)__bfloat16_as_ushort(__float2bfloat16(lz)) |
               ((uint32_t)__bfloat16_as_ushort(__float2bfloat16(lw)) << 16);
        *(uint2*)(sm + AH_OFF + m * APITCH + k4 * 8) = hv;
        *(uint2*)(sm + AL_OFF + m * APITCH + k4 * 8) = lv;
    }

    // ldmatrix per-thread base addresses
    const uint32_t aBase = sbase + AH_OFF +
        (uint32_t)((warp_m * 32 + (sub & 1) * 8 + r7) * APITCH) + (uint32_t)((sub >> 1) * 16);
    const uint32_t bRow =
        (uint32_t)((warp_n * 64 + (sub >> 1) * 8 + r7) * BPITCH) + (uint32_t)((sub & 1) * 16);

    float acc[2][8][4];
    #pragma unroll
    for (int mt = 0; mt < 2; mt++)
        #pragma unroll
        for (int nt = 0; nt < 8; nt++)
            #pragma unroll
            for (int q = 0; q < 4; q++) acc[mt][nt][q] = 0.f;

    float bS1[4], bS2[4];
    int   bI1[4];
    #pragma unroll
    for (int i = 0; i < 4; i++) { bS1[i] = CUDART_INF_F; bS2[i] = CUDART_INF_F; bI1[i] = 0; }

    // prologue: two chunks in flight (stages 0,1)
    issue_chunk(sbase, 0, tid);
    asm volatile("cp.async.commit_group;" ::: "memory");
    issue_chunk(sbase, 1, tid);
    asm volatile("cp.async.commit_group;" ::: "memory");

    for (int c = 0; c < 256; c++) {
        if (c < 255) asm volatile("cp.async.wait_group 1;" ::: "memory");
        else         asm volatile("cp.async.wait_group 0;" ::: "memory");
        __syncthreads();   // chunk c visible to all; all warps past compute(c-1)

        if (c + 2 < 256) {   // stage (c+2)%3 was last read at iter c-1: safe
            issue_chunk(sbase, c + 2, tid);
            asm volatile("cp.async.commit_group;" ::: "memory");
        }

        const uint32_t kA = (uint32_t)((c & 7) * 64);
        const uint32_t bStage = sbase + BB_OFF + (uint32_t)(c % NSTAGE) * BSTAGE;

        #pragma unroll
        for (int ks = 0; ks < 2; ks++) {
            uint32_t ah[2][4], al[2][4];
            #pragma unroll
            for (int mt = 0; mt < 2; mt++) {
                uint32_t a = aBase + (uint32_t)(mt * 16 * APITCH) + kA + ks * 32;
                ldsm4(ah[mt], a);
                ldsm4(al[mt], a + AL_OFF);
            }
            uint32_t bh[8][2], bl[8][2];
            #pragma unroll
            for (int p = 0; p < 4; p++) {
                uint32_t b = bStage + bRow + (uint32_t)(p * 16 * BPITCH) + ks * 32;
                uint32_t t[4];
                ldsm4(t, b);
                bh[2*p][0] = t[0]; bh[2*p][1] = t[1];
                bh[2*p+1][0] = t[2]; bh[2*p+1][1] = t[3];
                ldsm4(t, b + BLO);
                bl[2*p][0] = t[0]; bl[2*p][1] = t[1];
                bl[2*p+1][0] = t[2]; bl[2*p+1][1] = t[3];
            }
            #pragma unroll
            for (int mt = 0; mt < 2; mt++)
                #pragma unroll
                for (int nt = 0; nt < 8; nt++) {
                    mma16816(acc[mt][nt], ah[mt], bh[nt][0], bh[nt][1]);
                    mma16816(acc[mt][nt], ah[mt], bl[nt][0], bl[nt][1]);
                    mma16816(acc[mt][nt], al[mt], bh[nt][0], bh[nt][1]);
                }
        }

        if ((c & 7) == 7) {   // code tile complete: fold into best-2, reset acc
            const int n0 = (c >> 3) * 128;
            #pragma unroll
            for (int nt = 0; nt < 8; nt++) {
                int nb = n0 + warp_n * 64 + nt * 8 + tig * 2;
                float2 en = *(const float2*)&g_eNormHalf[nb];
                #pragma unroll
                for (int mt = 0; mt < 2; mt++) {
                    float s0 = en.x - acc[mt][nt][0];
                    float s1 = en.y - acc[mt][nt][1];
                    float s2 = en.x - acc[mt][nt][2];
                    float s3 = en.y - acc[mt][nt][3];
                    int lr0 = mt * 2, lr1 = mt * 2 + 1;
                    if (s0 < bS1[lr0]) { bS2[lr0] = bS1[lr0]; bS1[lr0] = s0; bI1[lr0] = nb; }
                    else if (s0 < bS2[lr0]) bS2[lr0] = s0;
                    if (s1 < bS1[lr0]) { bS2[lr0] = bS1[lr0]; bS1[lr0] = s1; bI1[lr0] = nb + 1; }
                    else if (s1 < bS2[lr0]) bS2[lr0] = s1;
                    if (s2 < bS1[lr1]) { bS2[lr1] = bS1[lr1]; bS1[lr1] = s2; bI1[lr1] = nb; }
                    else if (s2 < bS2[lr1]) bS2[lr1] = s2;
                    if (s3 < bS1[lr1]) { bS2[lr1] = bS1[lr1]; bS1[lr1] = s3; bI1[lr1] = nb + 1; }
                    else if (s3 < bS2[lr1]) bS2[lr1] = s3;
                    acc[mt][nt][0] = 0.f; acc[mt][nt][1] = 0.f;
                    acc[mt][nt][2] = 0.f; acc[mt][nt][3] = 0.f;
                }
            }
        }
    }
    __syncthreads();   // all compute done before reduction aliases B buffers

    // ---- cross-thread best-2 merge (8 slots per token row) ----
    float* rS1 = (float*)(sm + RED_OFF);
    float* rS2 = (float*)(sm + RED_OFF + 4096);
    int*   rI  = (int*)  (sm + RED_OFF + 8192);
    const int slot = warp_n * 4 + tig;
    #pragma unroll
    for (int lr = 0; lr < 4; lr++) {
        int r = warp_m * 32 + (lr >> 1) * 16 + (lr & 1) * 8 + gid;
        rS1[r * 8 + slot] = bS1[lr];
        rS2[r * 8 + slot] = bS2[lr];
        rI [r * 8 + slot] = bI1[lr];
    }
    __syncthreads();
    if (tid < 128) {
        float b1 = CUDART_INF_F, b2 = CUDART_INF_F;
        int bi = 0x7FFFFFFF;
        #pragma unroll
        for (int s = 0; s < 8; s++) {
            float s1 = rS1[tid * 8 + s];
            float s2 = rS2[tid * 8 + s];
            int   i1 = rI [tid * 8 + s];
            if (s1 < b1 || (s1 == b1 && i1 < bi)) {
                b2 = fminf(b2, fminf(b1, s2));
                b1 = s1; bi = i1;
            } else {
                b2 = fminf(b2, s1);
            }
        }
        g_idx[m0 + tid] = bi;
        if (b2 - b1 <= WINDOW) {
            int p = atomicAdd(&g_ambCount, 1);
            g_ambList[p] = m0 + tid;
        }
    }
}

// ---------------------------------------------------------------------------
// fixup: exact fp32 argmin for ambiguous tokens (lowest-index tie-break)
// ---------------------------------------------------------------------------
__global__ void fixup_kernel(const float* __restrict__ z, const float* __restrict__ e) {
    __shared__ __align__(16) float sz[D];
    __shared__ float rs[256];
    __shared__ int   ri[256];
    const int tid = threadIdx.x;
    const int cnt = g_ambCount;
    for (int li = blockIdx.x; li < cnt; li += gridDim.x) {
        int m = g_ambList[li];
        sz[tid] = z[(size_t)m * D + tid];
        __syncthreads();
        float bs = CUDART_INF_F;
        int   bi = 0x7FFFFFFF;
        for (int rep = 0; rep < NE / 256; rep++) {
            int n = rep * 256 + tid;
            float acc = 0.f;
            const float4* er = (const float4*)(e + (size_t)n * D);
            const float4* zr = (const float4*)sz;
            #pragma unroll 8
            for (int k4 = 0; k4 < D / 4; k4++) {
                float4 ee = er[k4], zz = zr[k4];
                acc = __fmaf_rn(zz.x, ee.x, acc);
                acc = __fmaf_rn(zz.y, ee.y, acc);
                acc = __fmaf_rn(zz.z, ee.z, acc);
                acc = __fmaf_rn(zz.w, ee.w, acc);
            }
            float s = g_eNormHalf[n] - acc;
            if (s < bs || (s == bs && n < bi)) { bs = s; bi = n; }
        }
        rs[tid] = bs; ri[tid] = bi;
        __syncthreads();
        if (tid == 0) {
            float b = rs[0]; int i = ri[0];
            for (int t = 1; t < 256; t++)
                if (rs[t] < b || (rs[t] == b && ri[t] < i)) { b = rs[t]; i = ri[t]; }
            g_idx[m] = i;
        }
        __syncthreads();
    }
}

// ---------------------------------------------------------------------------
// gather
// ---------------------------------------------------------------------------
__global__ void gather_kernel(const float* __restrict__ e,
                              float* __restrict__ out, int write_idx_tail) {
    int t   = blockIdx.x * blockDim.x + threadIdx.x;
    int row = t >> 6;
    int c   = t & 63;
    int idx = g_idx[row];
    ((float4*)out)[t] = ((const float4*)(e + (size_t)idx * D))[c];
    if (write_idx_tail && c == 0) out[NT * D + row] = (float)idx;
}

extern "C" void kernel_launch(void* const* d_in, const int* in_sizes, int n_in,
                              void* d_out, int out_size) {
    const float* z = (const float*)d_in[0];
    const float* e = (const float*)d_in[1];
    float* out = (float*)d_out;
    int write_idx_tail = (out_size >= NT * D + NT) ? 1 : 0;

    cudaFuncSetAttribute(argmin_mma, cudaFuncAttributeMaxDynamicSharedMemorySize, SMEM_TOTAL);

    enorm_kernel<<<NE / 8, 256>>>(e);
    esplit_kernel<<<(NE * D) / 256, 256>>>(e);
    argmin_mma<<<NT / 128, 256, SMEM_TOTAL>>>(z);
    fixup_kernel<<<512, 256>>>(z, e);
    gather_kernel<<<(NT * (D / 4)) / 256, 256>>>(e, out, write_idx_tail);
}

// round 7
// speedup vs baseline: 8.4868x; 2.5817x over previous
#include <cuda_runtime.h>
#include <cuda_fp16.h>
#include <cstdint>
#include <math_constants.h>

#define D       256
#define NT      65536
#define NE      4096
#define WINDOW  0.08f

// ---- smem layout (bytes) ----
#define APITCH  528                       // 264 halves per A row (256 data + 8 pad)
#define AH_OFF  0
#define BB_OFF  (128 * APITCH)            // 67584
#define BPITCH  80                        // 40 halves per B row (32 data + 8 pad)
#define BSTAGE  (128 * BPITCH)            // 10240
#define NSTAGE  3
#define RED_OFF BB_OFF                    // reduction arrays alias B stages
#define SMEM_TOTAL (BB_OFF + NSTAGE * BSTAGE)   // 98304 (96KB) -> 2 CTAs/SM

__device__ float  g_eNormHalf[NE];
__device__ int    g_idx[NT];
__device__ int    g_ambCount;
__device__ int    g_fullCount;
__device__ int    g_ambList[NT];
__device__ int    g_fullList[NT];
__device__ int    g_candList[NT * 16];
__device__ int    g_candCnt[NT];
__device__ float  g_candScore[NT * 16];
__device__ __half g_eH[NE * D];

// ---------------- helpers ----------------
__device__ __forceinline__ uint32_t smem_u32(const void* p) {
    uint32_t a;
    asm("{ .reg .u64 t; cvta.to.shared.u64 t, %1; cvt.u32.u64 %0, t; }" : "=r"(a) : "l"(p));
    return a;
}
__device__ __forceinline__ void ldsm4(uint32_t (&r)[4], uint32_t a) {
    asm volatile("ldmatrix.sync.aligned.m8n8.x4.shared.b16 {%0,%1,%2,%3}, [%4];"
                 : "=r"(r[0]), "=r"(r[1]), "=r"(r[2]), "=r"(r[3]) : "r"(a));
}
__device__ __forceinline__ void mma16816(float (&c)[4], const uint32_t (&a)[4],
                                         uint32_t b0, uint32_t b1) {
    asm volatile("mma.sync.aligned.m16n8k16.row.col.f32.f16.f16.f32 "
                 "{%0,%1,%2,%3}, {%4,%5,%6,%7}, {%8,%9}, {%0,%1,%2,%3};"
                 : "+f"(c[0]), "+f"(c[1]), "+f"(c[2]), "+f"(c[3])
                 : "r"(a[0]), "r"(a[1]), "r"(a[2]), "r"(a[3]), "r"(b0), "r"(b1));
}

// exact fp32 score in the VALIDATED order (matches reference argmin behavior)
__device__ __forceinline__ float exact_score(const float* __restrict__ zrow,
                                             const float* __restrict__ e, int n) {
    float acc = 0.f;
    const float4* er = (const float4*)(e + (size_t)n * D);
    const float4* zr = (const float4*)zrow;
    #pragma unroll 8
    for (int k4 = 0; k4 < D / 4; k4++) {
        float4 ee = er[k4], zz = zr[k4];
        acc = __fmaf_rn(zz.x, ee.x, acc);
        acc = __fmaf_rn(zz.y, ee.y, acc);
        acc = __fmaf_rn(zz.z, ee.z, acc);
        acc = __fmaf_rn(zz.w, ee.w, acc);
    }
    return g_eNormHalf[n] - acc;
}

// ---------------------------------------------------------------------------
// enorm: 0.5*||e||^2
// ---------------------------------------------------------------------------
__global__ void enorm_kernel(const float* __restrict__ e) {
    int row  = blockIdx.x * (blockDim.x >> 5) + (threadIdx.x >> 5);
    int lane = threadIdx.x & 31;
    const float4* p = (const float4*)(e + row * D);
    float s = 0.f;
    #pragma unroll
    for (int i = lane; i < D / 4; i += 32) {
        float4 v = p[i];
        s += v.x * v.x + v.y * v.y + v.z * v.z + v.w * v.w;
    }
    #pragma unroll
    for (int o = 16; o; o >>= 1) s += __shfl_xor_sync(0xFFFFFFFFu, s, o);
    if (lane == 0) g_eNormHalf[row] = 0.5f * s;
}

// ---------------------------------------------------------------------------
// e -> fp16 image; zero counters
// ---------------------------------------------------------------------------
__global__ void esplit_kernel(const float* __restrict__ e) {
    int idx = blockIdx.x * 256 + threadIdx.x;
    if (idx == 0) { g_ambCount = 0; g_fullCount = 0; }
    g_eH[idx] = __float2half_rn(e[idx]);
}

// ---------------------------------------------------------------------------
// cp.async fill of one e k-chunk (128 codes x 32 dims fp16) into stage c%3
// ---------------------------------------------------------------------------
__device__ __forceinline__ void issue_chunk(uint32_t sbase, int c, int tid) {
    const int n0 = (c >> 3) * 128;
    const int k0 = (c & 7) * 32;
    const uint32_t sb = sbase + BB_OFF + (uint32_t)(c % NSTAGE) * BSTAGE;
    #pragma unroll
    for (int j = 0; j < 2; j++) {
        int lin = tid + j * 256;            // 0..511
        int row = lin >> 2;
        int off = (lin & 3) * 16;
        const char* g = (const char*)g_eH + (size_t)(n0 + row) * (D * 2) + k0 * 2 + off;
        uint32_t s = sb + (uint32_t)(row * BPITCH) + off;
        asm volatile("cp.async.cg.shared.global [%0], [%1], 16;" :: "r"(s), "l"(g));
    }
}

// ---------------------------------------------------------------------------
// pass-1: fp16 single-MMA GEMM + best-2(+3rd value) candidate generation
// 256 threads, warps 4(m) x 2(n) over 128x128 output tiles.
// ---------------------------------------------------------------------------
__global__ __launch_bounds__(256, 2)
void argmin_mma(const float* __restrict__ z) {
    extern __shared__ unsigned char sm[];
    const uint32_t sbase = smem_u32(sm);

    const int tid  = threadIdx.x;
    const int lane = tid & 31, wid = tid >> 5;
    const int warp_m = wid & 3, warp_n = wid >> 2;
    const int gid = lane >> 2, tig = lane & 3;
    const int sub = lane >> 3, r7 = lane & 7;
    const int m0 = blockIdx.x * 128;

    // ---- z tile -> fp16 smem (row-major, padded) ----
    for (int i = tid; i < 128 * 64; i += 256) {
        int m = i >> 6, k4 = i & 63;
        float4 v = ((const float4*)(z + (size_t)(m0 + m) * D))[k4];
        uint2 hv;
        hv.x = (uint32_t)__half_as_ushort(__float2half_rn(v.x)) |
               ((uint32_t)__half_as_ushort(__float2half_rn(v.y)) << 16);
        hv.y = (uint32_t)__half_as_ushort(__float2half_rn(v.z)) |
               ((uint32_t)__half_as_ushort(__float2half_rn(v.w)) << 16);
        *(uint2*)(sm + AH_OFF + m * APITCH + k4 * 8) = hv;
    }

    const uint32_t aBase = sbase + AH_OFF +
        (uint32_t)((warp_m * 32 + (sub & 1) * 8 + r7) * APITCH) + (uint32_t)((sub >> 1) * 16);
    const uint32_t bRow =
        (uint32_t)((warp_n * 64 + (sub >> 1) * 8 + r7) * BPITCH) + (uint32_t)((sub & 1) * 16);

    float acc[2][8][4];
    #pragma unroll
    for (int mt = 0; mt < 2; mt++)
        #pragma unroll
        for (int nt = 0; nt < 8; nt++)
            #pragma unroll
            for (int q = 0; q < 4; q++) acc[mt][nt][q] = 0.f;

    float bS1[4], bS2[4], bS3[4];
    int   bI1[4], bI2[4];
    #pragma unroll
    for (int i = 0; i < 4; i++) {
        bS1[i] = CUDART_INF_F; bS2[i] = CUDART_INF_F; bS3[i] = CUDART_INF_F;
        bI1[i] = 0; bI2[i] = 0;
    }

    issue_chunk(sbase, 0, tid);
    asm volatile("cp.async.commit_group;" ::: "memory");
    issue_chunk(sbase, 1, tid);
    asm volatile("cp.async.commit_group;" ::: "memory");

    for (int c = 0; c < 256; c++) {
        if (c < 255) asm volatile("cp.async.wait_group 1;" ::: "memory");
        else         asm volatile("cp.async.wait_group 0;" ::: "memory");
        __syncthreads();

        if (c + 2 < 256) {
            issue_chunk(sbase, c + 2, tid);
            asm volatile("cp.async.commit_group;" ::: "memory");
        }

        const uint32_t kA = (uint32_t)((c & 7) * 64);
        const uint32_t bStage = sbase + BB_OFF + (uint32_t)(c % NSTAGE) * BSTAGE;

        #pragma unroll
        for (int ks = 0; ks < 2; ks++) {
            uint32_t ah[2][4];
            #pragma unroll
            for (int mt = 0; mt < 2; mt++)
                ldsm4(ah[mt], aBase + (uint32_t)(mt * 16 * APITCH) + kA + ks * 32);
            uint32_t bh[8][2];
            #pragma unroll
            for (int p = 0; p < 4; p++) {
                uint32_t t[4];
                ldsm4(t, bStage + bRow + (uint32_t)(p * 16 * BPITCH) + ks * 32);
                bh[2*p][0] = t[0]; bh[2*p][1] = t[1];
                bh[2*p+1][0] = t[2]; bh[2*p+1][1] = t[3];
            }
            #pragma unroll
            for (int mt = 0; mt < 2; mt++)
                #pragma unroll
                for (int nt = 0; nt < 8; nt++)
                    mma16816(acc[mt][nt], ah[mt], bh[nt][0], bh[nt][1]);
        }

        if ((c & 7) == 7) {   // fold code tile into best-3 (3rd value only)
            const int n0 = (c >> 3) * 128;
            #pragma unroll
            for (int nt = 0; nt < 8; nt++) {
                int nb = n0 + warp_n * 64 + nt * 8 + tig * 2;
                float2 en = *(const float2*)&g_eNormHalf[nb];
                #pragma unroll
                for (int mt = 0; mt < 2; mt++) {
                    #pragma unroll
                    for (int half = 0; half < 2; half++) {
                        int lr = mt * 2 + half;
                        float sa = (half ? en.x - acc[mt][nt][2] : en.x - acc[mt][nt][0]);
                        float sb2 = (half ? en.y - acc[mt][nt][3] : en.y - acc[mt][nt][1]);
                        if (sa < bS1[lr]) { bS3[lr] = bS2[lr]; bS2[lr] = bS1[lr]; bI2[lr] = bI1[lr]; bS1[lr] = sa; bI1[lr] = nb; }
                        else if (sa < bS2[lr]) { bS3[lr] = bS2[lr]; bS2[lr] = sa; bI2[lr] = nb; }
                        else if (sa < bS3[lr]) { bS3[lr] = sa; }
                        if (sb2 < bS1[lr]) { bS3[lr] = bS2[lr]; bS2[lr] = bS1[lr]; bI2[lr] = bI1[lr]; bS1[lr] = sb2; bI1[lr] = nb + 1; }
                        else if (sb2 < bS2[lr]) { bS3[lr] = bS2[lr]; bS2[lr] = sb2; bI2[lr] = nb + 1; }
                        else if (sb2 < bS3[lr]) { bS3[lr] = sb2; }
                    }
                    acc[mt][nt][0] = 0.f; acc[mt][nt][1] = 0.f;
                    acc[mt][nt][2] = 0.f; acc[mt][nt][3] = 0.f;
                }
            }
        }
    }
    __syncthreads();   // compute done; reduction aliases B stages

    float* rS1 = (float*)(sm + RED_OFF);
    int*   rI1 = (int*)  (sm + RED_OFF + 4096);
    float* rS2 = (float*)(sm + RED_OFF + 8192);
    int*   rI2 = (int*)  (sm + RED_OFF + 12288);
    float* rS3 = (float*)(sm + RED_OFF + 16384);
    const int slot = warp_n * 4 + tig;
    #pragma unroll
    for (int lr = 0; lr < 4; lr++) {
        int r = warp_m * 32 + (lr >> 1) * 16 + (lr & 1) * 8 + gid;
        rS1[r * 8 + slot] = bS1[lr];
        rI1[r * 8 + slot] = bI1[lr];
        rS2[r * 8 + slot] = bS2[lr];
        rI2[r * 8 + slot] = bI2[lr];
        rS3[r * 8 + slot] = bS3[lr];
    }
    __syncthreads();
    if (tid < 128) {
        const int m = m0 + tid;
        float gbs = CUDART_INF_F; int gbi = 0x7FFFFFFF;
        #pragma unroll
        for (int s = 0; s < 8; s++) {
            float v = rS1[tid * 8 + s]; int i = rI1[tid * 8 + s];
            if (v < gbs || (v == gbs && i < gbi)) { gbs = v; gbi = i; }
        }
        g_idx[m] = gbi;
        const float win = gbs + WINDOW;
        int cand[16]; int cc = 0; bool fallback = false;
        #pragma unroll
        for (int s = 0; s < 8; s++) {
            if (rS1[tid * 8 + s] <= win) cand[cc++] = rI1[tid * 8 + s];
            if (rS2[tid * 8 + s] <= win) cand[cc++] = rI2[tid * 8 + s];
            if (rS3[tid * 8 + s] <= win) fallback = true;
        }
        if (fallback) {
            int p = atomicAdd(&g_fullCount, 1);
            g_fullList[p] = m;
        } else if (cc > 1) {
            int p = atomicAdd(&g_ambCount, 1);
            g_ambList[p] = m;
            g_candCnt[p] = cc;
            for (int j = 0; j < cc; j++) g_candList[p * 16 + j] = cand[j];
        }
    }
}

// ---------------------------------------------------------------------------
// fixcand stage 1: exact fp32 score per (ambiguous token, candidate)
// ---------------------------------------------------------------------------
__global__ void fixcand_kernel(const float* __restrict__ z, const float* __restrict__ e) {
    const int cnt = g_ambCount;
    const int total = cnt * 16;
    for (int s = blockIdx.x * 256 + threadIdx.x; s < total; s += gridDim.x * 256) {
        int ti = s >> 4, ci = s & 15;
        if (ci >= g_candCnt[ti]) continue;
        int m = g_ambList[ti];
        int n = g_candList[s];
        g_candScore[s] = exact_score(z + (size_t)m * D, e, n);
    }
}

// ---------------------------------------------------------------------------
// fixcand stage 2: pick min (score, index) per ambiguous token
// ---------------------------------------------------------------------------
__global__ void fixpick_kernel() {
    const int cnt = g_ambCount;
    for (int ti = blockIdx.x * 256 + threadIdx.x; ti < cnt; ti += gridDim.x * 256) {
        int cc = g_candCnt[ti];
        float bs = CUDART_INF_F; int bi = 0x7FFFFFFF;
        for (int j = 0; j < cc; j++) {
            float s = g_candScore[ti * 16 + j];
            int   n = g_candList[ti * 16 + j];
            if (s < bs || (s == bs && n < bi)) { bs = s; bi = n; }
        }
        g_idx[g_ambList[ti]] = bi;
    }
}

// ---------------------------------------------------------------------------
// fallback: exact full-scan for tokens with possible hidden candidates (rare)
// ---------------------------------------------------------------------------
__global__ void fixfull_kernel(const float* __restrict__ z, const float* __restrict__ e) {
    __shared__ __align__(16) float sz[D];
    __shared__ float rs[256];
    __shared__ int   ri[256];
    const int tid = threadIdx.x;
    const int cnt = g_fullCount;
    for (int li = blockIdx.x; li < cnt; li += gridDim.x) {
        int m = g_fullList[li];
        sz[tid] = z[(size_t)m * D + tid];
        __syncthreads();
        float bs = CUDART_INF_F;
        int   bi = 0x7FFFFFFF;
        for (int rep = 0; rep < NE / 256; rep++) {
            int n = rep * 256 + tid;
            float s = exact_score(sz, e, n);
            if (s < bs || (s == bs && n < bi)) { bs = s; bi = n; }
        }
        rs[tid] = bs; ri[tid] = bi;
        __syncthreads();
        if (tid == 0) {
            float b = rs[0]; int i = ri[0];
            for (int t = 1; t < 256; t++)
                if (rs[t] < b || (rs[t] == b && ri[t] < i)) { b = rs[t]; i = ri[t]; }
            g_idx[m] = i;
        }
        __syncthreads();
    }
}

// ---------------------------------------------------------------------------
// gather
// ---------------------------------------------------------------------------
__global__ void gather_kernel(const float* __restrict__ e,
                              float* __restrict__ out, int write_idx_tail) {
    int t   = blockIdx.x * blockDim.x + threadIdx.x;
    int row = t >> 6;
    int c   = t & 63;
    int idx = g_idx[row];
    ((float4*)out)[t] = ((const float4*)(e + (size_t)idx * D))[c];
    if (write_idx_tail && c == 0) out[NT * D + row] = (float)idx;
}

extern "C" void kernel_launch(void* const* d_in, const int* in_sizes, int n_in,
                              void* d_out, int out_size) {
    const float* z = (const float*)d_in[0];
    const float* e = (const float*)d_in[1];
    float* out = (float*)d_out;
    int write_idx_tail = (out_size >= NT * D + NT) ? 1 : 0;

    cudaFuncSetAttribute(argmin_mma, cudaFuncAttributeMaxDynamicSharedMemorySize, SMEM_TOTAL);

    enorm_kernel<<<NE / 8, 256>>>(e);
    esplit_kernel<<<(NE * D) / 256, 256>>>(e);
    argmin_mma<<<NT / 128, 256, SMEM_TOTAL>>>(z);
    fixcand_kernel<<<128, 256>>>(z, e);
    fixpick_kernel<<<32, 256>>>();
    fixfull_kernel<<<64, 256>>>(z, e);
    gather_kernel<<<(NT * (D / 4)) / 256, 256>>>(e, out, write_idx_tail);
}

// round 8
// speedup vs baseline: 9.1011x; 1.0724x over previous
#include <cuda_runtime.h>
#include <cuda_fp16.h>
#include <cstdint>
#include <math_constants.h>

#define D       256
#define NT      65536
#define NE      4096
#define WINDOW  0.08f

// ---- smem layout (bytes) ----
#define APITCH  528                       // 264 halves per A row (256 data + 8 pad)
#define AH_OFF  0
#define BB_OFF  (128 * APITCH)            // 67584
#define BPITCH  144                       // 72 halves per B row (64 data + 8 pad); 144=9*16 -> conflict-free
#define BSTAGE  (128 * BPITCH)            // 18432
#define NSTAGE  2
#define RED_OFF BB_OFF                    // reduction arrays alias B stages
#define SMEM_TOTAL (BB_OFF + NSTAGE * BSTAGE)   // 104448 (~102KB) -> 2 CTAs/SM

__device__ float  g_eNormHalf[NE];
__device__ int    g_idx[NT];
__device__ int    g_ambCount;
__device__ int    g_fullCount;
__device__ int    g_ambList[NT];
__device__ int    g_fullList[NT];
__device__ int    g_candList[NT * 16];
__device__ int    g_candCnt[NT];
__device__ __half g_eH[NE * D];

// ---------------- helpers ----------------
__device__ __forceinline__ uint32_t smem_u32(const void* p) {
    uint32_t a;
    asm("{ .reg .u64 t; cvta.to.shared.u64 t, %1; cvt.u32.u64 %0, t; }" : "=r"(a) : "l"(p));
    return a;
}
__device__ __forceinline__ void ldsm4(uint32_t (&r)[4], uint32_t a) {
    asm volatile("ldmatrix.sync.aligned.m8n8.x4.shared.b16 {%0,%1,%2,%3}, [%4];"
                 : "=r"(r[0]), "=r"(r[1]), "=r"(r[2]), "=r"(r[3]) : "r"(a));
}
__device__ __forceinline__ void mma16816(float (&c)[4], const uint32_t (&a)[4],
                                         uint32_t b0, uint32_t b1) {
    asm volatile("mma.sync.aligned.m16n8k16.row.col.f32.f16.f16.f32 "
                 "{%0,%1,%2,%3}, {%4,%5,%6,%7}, {%8,%9}, {%0,%1,%2,%3};"
                 : "+f"(c[0]), "+f"(c[1]), "+f"(c[2]), "+f"(c[3])
                 : "r"(a[0]), "r"(a[1]), "r"(a[2]), "r"(a[3]), "r"(b0), "r"(b1));
}

// exact fp32 score in the VALIDATED order (matches reference argmin behavior)
__device__ __forceinline__ float exact_score(const float* __restrict__ zrow,
                                             const float* __restrict__ e, int n) {
    float acc = 0.f;
    const float4* er = (const float4*)(e + (size_t)n * D);
    const float4* zr = (const float4*)zrow;
    #pragma unroll 8
    for (int k4 = 0; k4 < D / 4; k4++) {
        float4 ee = er[k4], zz = zr[k4];
        acc = __fmaf_rn(zz.x, ee.x, acc);
        acc = __fmaf_rn(zz.y, ee.y, acc);
        acc = __fmaf_rn(zz.z, ee.z, acc);
        acc = __fmaf_rn(zz.w, ee.w, acc);
    }
    return g_eNormHalf[n] - acc;
}

// ---------------------------------------------------------------------------
// prep: 0.5*||e||^2 AND fp16 image of e in one pass; zero counters.
// one warp per codebook row.
// ---------------------------------------------------------------------------
__global__ void prep_kernel(const float* __restrict__ e) {
    int row  = blockIdx.x * (blockDim.x >> 5) + (threadIdx.x >> 5);
    int lane = threadIdx.x & 31;
    if (blockIdx.x == 0 && threadIdx.x == 0) { g_ambCount = 0; g_fullCount = 0; }
    const float4* p = (const float4*)(e + (size_t)row * D);
    float s = 0.f;
    #pragma unroll
    for (int i = 0; i < 2; i++) {
        int c4 = lane + i * 32;
        float4 v = p[c4];
        s += v.x * v.x + v.y * v.y + v.z * v.z + v.w * v.w;
        uint2 hv;
        hv.x = (uint32_t)__half_as_ushort(__float2half_rn(v.x)) |
               ((uint32_t)__half_as_ushort(__float2half_rn(v.y)) << 16);
        hv.y = (uint32_t)__half_as_ushort(__float2half_rn(v.z)) |
               ((uint32_t)__half_as_ushort(__float2half_rn(v.w)) << 16);
        *(uint2*)(g_eH + (size_t)row * D + c4 * 4) = hv;
    }
    #pragma unroll
    for (int o = 16; o; o >>= 1) s += __shfl_xor_sync(0xFFFFFFFFu, s, o);
    if (lane == 0) g_eNormHalf[row] = 0.5f * s;
}

// ---------------------------------------------------------------------------
// cp.async fill of one e k-chunk (128 codes x 64 dims fp16) into stage c%2
// ---------------------------------------------------------------------------
__device__ __forceinline__ void issue_chunk(uint32_t sbase, int c, int tid) {
    const int n0 = (c >> 2) * 128;
    const int k0 = (c & 3) * 64;
    const uint32_t sb = sbase + BB_OFF + (uint32_t)(c & 1) * BSTAGE;
    #pragma unroll
    for (int j = 0; j < 4; j++) {
        int lin = tid + j * 256;            // 0..1023
        int row = lin >> 3;
        int off = (lin & 7) * 16;
        const char* g = (const char*)g_eH + (size_t)(n0 + row) * (D * 2) + k0 * 2 + off;
        uint32_t s = sb + (uint32_t)(row * BPITCH) + off;
        asm volatile("cp.async.cg.shared.global [%0], [%1], 16;" :: "r"(s), "l"(g));
    }
}

// ---------------------------------------------------------------------------
// pass-1: fp16 single-MMA GEMM + best-2(+3rd value) candidate generation
// 256 threads, warps 4(m) x 2(n) over 128x128 output tiles. k64 chunks,
// 2-stage cp.async pipeline, one __syncthreads per chunk.
// ---------------------------------------------------------------------------
__global__ __launch_bounds__(256, 2)
void argmin_mma(const float* __restrict__ z) {
    extern __shared__ unsigned char sm[];
    const uint32_t sbase = smem_u32(sm);

    const int tid  = threadIdx.x;
    const int lane = tid & 31, wid = tid >> 5;
    const int warp_m = wid & 3, warp_n = wid >> 2;
    const int gid = lane >> 2, tig = lane & 3;
    const int sub = lane >> 3, r7 = lane & 7;
    const int m0 = blockIdx.x * 128;

    // ---- z tile -> fp16 smem (row-major, padded) ----
    for (int i = tid; i < 128 * 64; i += 256) {
        int m = i >> 6, k4 = i & 63;
        float4 v = ((const float4*)(z + (size_t)(m0 + m) * D))[k4];
        uint2 hv;
        hv.x = (uint32_t)__half_as_ushort(__float2half_rn(v.x)) |
               ((uint32_t)__half_as_ushort(__float2half_rn(v.y)) << 16);
        hv.y = (uint32_t)__half_as_ushort(__float2half_rn(v.z)) |
               ((uint32_t)__half_as_ushort(__float2half_rn(v.w)) << 16);
        *(uint2*)(sm + AH_OFF + m * APITCH + k4 * 8) = hv;
    }

    const uint32_t aBase = sbase + AH_OFF +
        (uint32_t)((warp_m * 32 + (sub & 1) * 8 + r7) * APITCH) + (uint32_t)((sub >> 1) * 16);
    const uint32_t bRow =
        (uint32_t)((warp_n * 64 + (sub >> 1) * 8 + r7) * BPITCH) + (uint32_t)((sub & 1) * 16);

    float acc[2][8][4];
    #pragma unroll
    for (int mt = 0; mt < 2; mt++)
        #pragma unroll
        for (int nt = 0; nt < 8; nt++)
            #pragma unroll
            for (int q = 0; q < 4; q++) acc[mt][nt][q] = 0.f;

    float bS1[4], bS2[4], bS3[4];
    int   bI1[4], bI2[4];
    #pragma unroll
    for (int i = 0; i < 4; i++) {
        bS1[i] = CUDART_INF_F; bS2[i] = CUDART_INF_F; bS3[i] = CUDART_INF_F;
        bI1[i] = 0; bI2[i] = 0;
    }

    issue_chunk(sbase, 0, tid);
    asm volatile("cp.async.commit_group;" ::: "memory");

    for (int c = 0; c < 128; c++) {
        asm volatile("cp.async.wait_group 0;" ::: "memory");
        __syncthreads();   // chunk c resident & visible; all warps past compute(c-1)

        if (c + 1 < 128) {   // other stage last read at compute(c-1): safe
            issue_chunk(sbase, c + 1, tid);
            asm volatile("cp.async.commit_group;" ::: "memory");
        }

        const uint32_t kA = (uint32_t)((c & 3) * 128);
        const uint32_t bStage = sbase + BB_OFF + (uint32_t)(c & 1) * BSTAGE;

        #pragma unroll
        for (int ks = 0; ks < 4; ks++) {
            uint32_t ah[2][4];
            #pragma unroll
            for (int mt = 0; mt < 2; mt++)
                ldsm4(ah[mt], aBase + (uint32_t)(mt * 16 * APITCH) + kA + ks * 32);
            uint32_t bh[8][2];
            #pragma unroll
            for (int p = 0; p < 4; p++) {
                uint32_t t[4];
                ldsm4(t, bStage + bRow + (uint32_t)(p * 16 * BPITCH) + ks * 32);
                bh[2*p][0] = t[0]; bh[2*p][1] = t[1];
                bh[2*p+1][0] = t[2]; bh[2*p+1][1] = t[3];
            }
            #pragma unroll
            for (int mt = 0; mt < 2; mt++)
                #pragma unroll
                for (int nt = 0; nt < 8; nt++)
                    mma16816(acc[mt][nt], ah[mt], bh[nt][0], bh[nt][1]);
        }

        if ((c & 3) == 3) {   // code tile complete: fold into best-3, reset acc
            const int n0 = (c >> 2) * 128;
            #pragma unroll
            for (int nt = 0; nt < 8; nt++) {
                int nb = n0 + warp_n * 64 + nt * 8 + tig * 2;
                float2 en = *(const float2*)&g_eNormHalf[nb];
                #pragma unroll
                for (int mt = 0; mt < 2; mt++) {
                    #pragma unroll
                    for (int half = 0; half < 2; half++) {
                        int lr = mt * 2 + half;
                        float sa = (half ? en.x - acc[mt][nt][2] : en.x - acc[mt][nt][0]);
                        float sb2 = (half ? en.y - acc[mt][nt][3] : en.y - acc[mt][nt][1]);
                        if (sa < bS1[lr]) { bS3[lr] = bS2[lr]; bS2[lr] = bS1[lr]; bI2[lr] = bI1[lr]; bS1[lr] = sa; bI1[lr] = nb; }
                        else if (sa < bS2[lr]) { bS3[lr] = bS2[lr]; bS2[lr] = sa; bI2[lr] = nb; }
                        else if (sa < bS3[lr]) { bS3[lr] = sa; }
                        if (sb2 < bS1[lr]) { bS3[lr] = bS2[lr]; bS2[lr] = bS1[lr]; bI2[lr] = bI1[lr]; bS1[lr] = sb2; bI1[lr] = nb + 1; }
                        else if (sb2 < bS2[lr]) { bS3[lr] = bS2[lr]; bS2[lr] = sb2; bI2[lr] = nb + 1; }
                        else if (sb2 < bS3[lr]) { bS3[lr] = sb2; }
                    }
                    acc[mt][nt][0] = 0.f; acc[mt][nt][1] = 0.f;
                    acc[mt][nt][2] = 0.f; acc[mt][nt][3] = 0.f;
                }
            }
        }
    }
    __syncthreads();   // compute done; reduction aliases B stages

    float* rS1 = (float*)(sm + RED_OFF);
    int*   rI1 = (int*)  (sm + RED_OFF + 4096);
    float* rS2 = (float*)(sm + RED_OFF + 8192);
    int*   rI2 = (int*)  (sm + RED_OFF + 12288);
    float* rS3 = (float*)(sm + RED_OFF + 16384);
    const int slot = warp_n * 4 + tig;
    #pragma unroll
    for (int lr = 0; lr < 4; lr++) {
        int r = warp_m * 32 + (lr >> 1) * 16 + (lr & 1) * 8 + gid;
        rS1[r * 8 + slot] = bS1[lr];
        rI1[r * 8 + slot] = bI1[lr];
        rS2[r * 8 + slot] = bS2[lr];
        rI2[r * 8 + slot] = bI2[lr];
        rS3[r * 8 + slot] = bS3[lr];
    }
    __syncthreads();
    if (tid < 128) {
        const int m = m0 + tid;
        float gbs = CUDART_INF_F; int gbi = 0x7FFFFFFF;
        #pragma unroll
        for (int s = 0; s < 8; s++) {
            float v = rS1[tid * 8 + s]; int i = rI1[tid * 8 + s];
            if (v < gbs || (v == gbs && i < gbi)) { gbs = v; gbi = i; }
        }
        g_idx[m] = gbi;
        const float win = gbs + WINDOW;
        int cand[16]; int cc = 0; bool fallback = false;
        #pragma unroll
        for (int s = 0; s < 8; s++) {
            if (rS1[tid * 8 + s] <= win) cand[cc++] = rI1[tid * 8 + s];
            if (rS2[tid * 8 + s] <= win) cand[cc++] = rI2[tid * 8 + s];
            if (rS3[tid * 8 + s] <= win) fallback = true;
        }
        if (fallback) {
            int p = atomicAdd(&g_fullCount, 1);
            g_fullList[p] = m;
        } else if (cc > 1) {
            int p = atomicAdd(&g_ambCount, 1);
            g_ambList[p] = m;
            g_candCnt[p] = cc;
            for (int j = 0; j < cc; j++) g_candList[p * 16 + j] = cand[j];
        }
    }
}

// ---------------------------------------------------------------------------
// fixcand: exact fp32 score per candidate + 16-lane min-reduce, writes g_idx.
// 16 consecutive threads own one ambiguous token.
// ---------------------------------------------------------------------------
__global__ void fixcand_kernel(const float* __restrict__ z, const float* __restrict__ e) {
    const int cnt = g_ambCount;
    const int gsz = (gridDim.x * 256) >> 4;
    const int ci  = threadIdx.x & 15;
    for (int ti = (blockIdx.x * 256 + threadIdx.x) >> 4; ti < cnt; ti += gsz) {
        int m  = g_ambList[ti];
        int cc = g_candCnt[ti];
        float s = CUDART_INF_F;
        int   n = 0x7FFFFFFF;
        if (ci < cc) {
            n = g_candList[ti * 16 + ci];
            s = exact_score(z + (size_t)m * D, e, n);
        }
        // pack (ordered-score, idx) into u64; min over 16 lanes
        uint32_t fb = __float_as_uint(s);
        fb = (fb & 0x80000000u) ? ~fb : (fb | 0x80000000u);
        unsigned long long key = ((unsigned long long)fb << 32) | (uint32_t)n;
        #pragma unroll
        for (int o = 8; o; o >>= 1) {
            unsigned long long other = __shfl_xor_sync(0xFFFFFFFFu, key, o);
            if (other < key) key = other;
        }
        if (ci == 0) g_idx[m] = (int)(key & 0xFFFFFFFFu);
    }
}

// ---------------------------------------------------------------------------
// fallback: exact full-scan for tokens with possible hidden candidates (rare)
// ---------------------------------------------------------------------------
__global__ void fixfull_kernel(const float* __restrict__ z, const float* __restrict__ e) {
    __shared__ __align__(16) float sz[D];
    __shared__ float rs[256];
    __shared__ int   ri[256];
    const int tid = threadIdx.x;
    const int cnt = g_fullCount;
    for (int li = blockIdx.x; li < cnt; li += gridDim.x) {
        int m = g_fullList[li];
        sz[tid] = z[(size_t)m * D + tid];
        __syncthreads();
        float bs = CUDART_INF_F;
        int   bi = 0x7FFFFFFF;
        for (int rep = 0; rep < NE / 256; rep++) {
            int n = rep * 256 + tid;
            float s = exact_score(sz, e, n);
            if (s < bs || (s == bs && n < bi)) { bs = s; bi = n; }
        }
        rs[tid] = bs; ri[tid] = bi;
        __syncthreads();
        if (tid == 0) {
            float b = rs[0]; int i = ri[0];
            for (int t = 1; t < 256; t++)
                if (rs[t] < b || (rs[t] == b && ri[t] < i)) { b = rs[t]; i = ri[t]; }
            g_idx[m] = i;
        }
        __syncthreads();
    }
}

// ---------------------------------------------------------------------------
// gather
// ---------------------------------------------------------------------------
__global__ void gather_kernel(const float* __restrict__ e,
                              float* __restrict__ out, int write_idx_tail) {
    int t   = blockIdx.x * blockDim.x + threadIdx.x;
    int row = t >> 6;
    int c   = t & 63;
    int idx = g_idx[row];
    ((float4*)out)[t] = ((const float4*)(e + (size_t)idx * D))[c];
    if (write_idx_tail && c == 0) out[NT * D + row] = (float)idx;
}

extern "C" void kernel_launch(void* const* d_in, const int* in_sizes, int n_in,
                              void* d_out, int out_size) {
    const float* z = (const float*)d_in[0];
    const float* e = (const float*)d_in[1];
    float* out = (float*)d_out;
    int write_idx_tail = (out_size >= NT * D + NT) ? 1 : 0;

    cudaFuncSetAttribute(argmin_mma, cudaFuncAttributeMaxDynamicSharedMemorySize, SMEM_TOTAL);

    prep_kernel<<<NE / 8, 256>>>(e);
    argmin_mma<<<NT / 128, 256, SMEM_TOTAL>>>(z);
    fixcand_kernel<<<148, 256>>>(z, e);
    fixfull_kernel<<<64, 256>>>(z, e);
    gather_kernel<<<(NT * (D / 4)) / 256, 256>>>(e, out, write_idx_tail);
}